// round 1
// baseline (speedup 1.0000x reference)
#include <cuda_runtime.h>
#include <math.h>

// Problem constants
#define SBK   2048
#define PASTK 64
#define FUTK  16
#define NK    80
#define N1K   (SBK*PASTK)   // 131072 nodes graph1
#define N2K   (SBK*FUTK)    // 32768 nodes graph2

// ---------------- device scratch (allocation-free rule: __device__ globals) ----
__device__ float g_x[N1K*35];      // pre output for x1 (stride 35)
__device__ float g_x2p[N2K*35];    // pre output for x2 (stride 35)
__device__ float g_bufA[N1K*64];   // h
__device__ float g_bufB[N1K*64];   // agg
__device__ float g_bufC[N1K*64];   // relu/finalized
__device__ float g_dinv1[N1K];
__device__ float g_dinv2[N2K];
__device__ float g_theta[34*34];
__device__ float g_x2n[N2K*35];    // x2 updated (last channel = yh)

// ---------------- A = softmax(tril-masked relu(M M^T)) -------------------------
__global__ void a_kernel(const float* __restrict__ M, float* __restrict__ A)
{
    __shared__ float sM[80*26];
    int tid = threadIdx.x;
    for (int i = tid; i < 80*26; i += blockDim.x) sM[i] = M[i];
    __syncthreads();
    if (tid < 80) {
        int i = tid;
        float mx = -INFINITY;
        for (int j = 0; j <= i; j++) {
            float s = 0.f;
            #pragma unroll
            for (int k = 0; k < 26; k++) s = fmaf(sM[i*26+k], sM[j*26+k], s);
            s = fmaxf(s, 0.f);
            mx = fmaxf(mx, s);
        }
        float sum = 0.f;
        for (int j = 0; j <= i; j++) {
            float s = 0.f;
            #pragma unroll
            for (int k = 0; k < 26; k++) s = fmaf(sM[i*26+k], sM[j*26+k], s);
            s = fmaxf(s, 0.f);
            float e = expf(s - mx);
            sum += e;
            A[i*80+j] = e;
        }
        float inv = 1.f / sum;
        for (int j = 0; j <= i; j++) A[i*80+j] *= inv;
        for (int j = i+1; j < 80; j++) A[i*80+j] = 0.f;
    }
}

// ---------------- theta = kerW kerW^T (symmetric by construction) --------------
__global__ void theta_kernel(const float* __restrict__ kerW, float* __restrict__ th)
{
    int idx = blockIdx.x*blockDim.x + threadIdx.x;
    if (idx < 34*34) {
        int i = idx / 34, j = idx - i*34;
        float s = 0.f;
        #pragma unroll 8
        for (int k = 0; k < 128; k++) s = fmaf(kerW[i*128+k], kerW[j*128+k], s);
        th[idx] = s;
    }
}

// ---------------- pre MLP: embed-gather + 35->128->128->34 (+passthrough num2) -
// warp per row; weights in dynamic smem (~104 KB => 2 CTAs/SM)
__global__ void pre_kernel(const int* __restrict__ cat, const float* __restrict__ num,
                           int nrows,
                           const float* __restrict__ W1, const float* __restrict__ b1,
                           const float* __restrict__ W2, const float* __restrict__ b2,
                           const float* __restrict__ W3, const float* __restrict__ b3,
                           const float* __restrict__ emb0, const float* __restrict__ emb1,
                           const float* __restrict__ emb2, float* __restrict__ out)
{
    extern __shared__ float smem[];
    float* sW1 = smem;               // 35*128 = 4480
    float* sW2 = sW1 + 35*128;       // 16384
    float* sW3 = sW2 + 128*128;      // 128*34 = 4352
    float* sb1 = sW3 + 128*34;       // 128
    float* sb2 = sb1 + 128;          // 128
    float* sb3 = sb2 + 128;          // 48 (34 used, padded for alignment)
    float* sh  = sb3 + 48;           // nwarps*128
    int tid = threadIdx.x;
    for (int i = tid; i < 35*128;  i += blockDim.x) sW1[i] = W1[i];
    for (int i = tid; i < 128*128; i += blockDim.x) sW2[i] = W2[i];
    for (int i = tid; i < 128*34;  i += blockDim.x) sW3[i] = W3[i];
    if (tid < 128) { sb1[tid] = b1[tid]; sb2[tid] = b2[tid]; }
    if (tid < 34) sb3[tid] = b3[tid];
    __syncthreads();
    const int lane = tid & 31, warp = tid >> 5, nw = blockDim.x >> 5;
    float* hrow = sh + warp*128;
    for (int r = blockIdx.x*nw + warp; r < nrows; r += gridDim.x*nw) {
        int c0 = cat[3*r], c1 = cat[3*r+1], c2 = cat[3*r+2];
        float oa, ob = 0.f;
        if (lane < 16)      oa = emb0[c0*16 + lane];
        else if (lane < 24) oa = emb1[c1*8 + lane - 16];
        else                oa = emb2[c2*8 + lane - 24];
        if (lane < 3) ob = num[3*r + lane];
        // layer 1: 35 -> 128, lane owns cols [4*lane, 4*lane+3]
        float4 a = ((const float4*)sb1)[lane];
        #pragma unroll
        for (int k = 0; k < 35; k++) {
            float xv = (k < 32) ? __shfl_sync(0xffffffffu, oa, k)
                                : __shfl_sync(0xffffffffu, ob, k - 32);
            float4 w = ((const float4*)(sW1 + k*128))[lane];
            a.x = fmaf(xv, w.x, a.x); a.y = fmaf(xv, w.y, a.y);
            a.z = fmaf(xv, w.z, a.z); a.w = fmaf(xv, w.w, a.w);
        }
        a.x = fmaxf(a.x,0.f); a.y = fmaxf(a.y,0.f); a.z = fmaxf(a.z,0.f); a.w = fmaxf(a.w,0.f);
        ((float4*)hrow)[lane] = a;
        __syncwarp();
        // layer 2: 128 -> 128
        float4 b = ((const float4*)sb2)[lane];
        #pragma unroll 8
        for (int k = 0; k < 128; k++) {
            float hv = hrow[k];
            float4 w = ((const float4*)(sW2 + k*128))[lane];
            b.x = fmaf(hv, w.x, b.x); b.y = fmaf(hv, w.y, b.y);
            b.z = fmaf(hv, w.z, b.z); b.w = fmaf(hv, w.w, b.w);
        }
        b.x = fmaxf(b.x,0.f); b.y = fmaxf(b.y,0.f); b.z = fmaxf(b.z,0.f); b.w = fmaxf(b.w,0.f);
        __syncwarp();
        ((float4*)hrow)[lane] = b;
        __syncwarp();
        // layer 3: 128 -> 34
        float acc0 = 0.f, acc1 = 0.f;
        const int j0 = lane, j1 = lane + 32;
        const bool has1 = (j1 < 34);
        #pragma unroll 8
        for (int k = 0; k < 128; k++) {
            float hv = hrow[k];
            acc0 = fmaf(hv, sW3[k*34 + j0], acc0);
            if (has1) acc1 = fmaf(hv, sW3[k*34 + j1], acc1);
        }
        float n2v = __shfl_sync(0xffffffffu, ob, 2);
        float* orow = out + (size_t)r*35;
        orow[j0] = acc0 + sb3[j0];            // lanes 0..31 -> cols 0..31
        if (has1) orow[j1] = acc1 + sb3[j1];  // lanes 0..1 -> cols 32..33
        if (lane == 0) orow[34] = n2v;        // passthrough num[:, -1]
        __syncwarp();
    }
}

// ---------------- degree kernels ----------------------------------------------
__global__ void deg_init_kernel(float* __restrict__ d, int n)
{
    for (int i = blockIdx.x*blockDim.x + threadIdx.x; i < n; i += gridDim.x*blockDim.x)
        d[i] = 1.0f;
}
__global__ void deg_count_kernel(const int* __restrict__ dst, int E, float* __restrict__ d)
{
    int e = blockIdx.x*blockDim.x + threadIdx.x;
    if (e < E) atomicAdd(&d[dst[e]], 1.0f);
}
__global__ void deg_rsqrt_kernel(float* __restrict__ d, int n)
{
    for (int i = blockIdx.x*blockDim.x + threadIdx.x; i < n; i += gridDim.x*blockDim.x)
        d[i] = rsqrtf(d[i]);
}

// ---------------- GCN: h = x@W, agg init = h * dinv^2 --------------------------
__global__ void gcn_mm_kernel(const float* __restrict__ x, int strideIn, int din,
                              const float* __restrict__ W, int dout,
                              const float* __restrict__ dinv, int n,
                              float* __restrict__ h, float* __restrict__ agg, int strideOut)
{
    __shared__ float sW[64*64];
    int tid = threadIdx.x;
    for (int i = tid; i < din*dout; i += blockDim.x) sW[i] = W[i];
    __syncthreads();
    const int lane = tid & 31, warp = tid >> 5, nw = blockDim.x >> 5;
    for (int r = blockIdx.x*nw + warp; r < n; r += gridDim.x*nw) {
        const float* xr = x + (size_t)r*strideIn;
        float xa = (lane < din)      ? xr[lane]      : 0.f;
        float xb = (lane + 32 < din) ? xr[lane + 32] : 0.f;
        float di = dinv[r]; float d2 = di*di;
        if (dout == 1) {
            float s = xa * sW[lane];
            if (lane + 32 < din) s = fmaf(xb, sW[lane+32], s);
            #pragma unroll
            for (int off = 16; off; off >>= 1) s += __shfl_xor_sync(0xffffffffu, s, off);
            if (lane == 0) { h[r] = s; agg[r] = s*d2; }
        } else {
            float acc0 = 0.f, acc1 = 0.f;
            const int j0 = lane, j1 = lane + 32;
            const bool has1 = (j1 < dout);
            for (int k = 0; k < din; k++) {
                float xv = (k < 32) ? __shfl_sync(0xffffffffu, xa, k)
                                    : __shfl_sync(0xffffffffu, xb, k - 32);
                acc0 = fmaf(xv, sW[k*dout + j0], acc0);
                if (has1) acc1 = fmaf(xv, sW[k*dout + j1], acc1);
            }
            float* hr = h   + (size_t)r*strideOut;
            float* ar = agg + (size_t)r*strideOut;
            hr[j0] = acc0; ar[j0] = acc0*d2;
            if (has1) { hr[j1] = acc1; ar[j1] = acc1*d2; }
        }
    }
}

// ---------------- GCN edge scatter: agg[dst] += h[src]*dinv[src]*dinv[dst] -----
__global__ void edge_kernel(const int* __restrict__ src, const int* __restrict__ dst, int E,
                            const float* __restrict__ dinv, const float* __restrict__ h,
                            float* __restrict__ agg, int dout, int stride)
{
    int e = blockIdx.x*blockDim.x + threadIdx.x;
    if (e >= E) return;
    int s = src[e], d = dst[e];
    float coef = dinv[s]*dinv[d];
    const float* hp = h   + (size_t)s*stride;
    float*       ap = agg + (size_t)d*stride;
    if (dout == 1) { atomicAdd(ap, hp[0]*coef); return; }
    int c4 = dout & ~3;
    for (int c = 0; c < c4; c += 4) {
        float4 v = *(const float4*)(hp + c);
        atomicAdd(ap + c + 0, v.x*coef);
        atomicAdd(ap + c + 1, v.y*coef);
        atomicAdd(ap + c + 2, v.z*coef);
        atomicAdd(ap + c + 3, v.w*coef);
    }
    for (int c = c4; c < dout; c++) atomicAdd(ap + c, hp[c]*coef);
}

// ---------------- finalize: y = (agg + b) [relu] --------------------------------
__global__ void finalize_kernel(const float* __restrict__ agg, const float* __restrict__ b,
                                float* __restrict__ y, int n, int dout,
                                int strideIn, int strideOut, int doRelu)
{
    int total = n*dout;
    for (int idx = blockIdx.x*blockDim.x + threadIdx.x; idx < total; idx += gridDim.x*blockDim.x) {
        int r = idx / dout, c = idx - r*dout;
        float v = agg[(size_t)r*strideIn + c] + b[c];
        if (doRelu) v = fmaxf(v, 0.f);
        y[(size_t)r*strideOut + c] = v;
    }
}

// ---------------- alpha / softmax / yh / build x2new ---------------------------
// one block per batch (2048 blocks, 128 threads)
__global__ void alpha_kernel(const float* __restrict__ x1g /*stride 36*/,
                             const float* __restrict__ x2p /*stride 35*/,
                             const float* __restrict__ xfull /*stride 35*/,
                             const float* __restrict__ theta,
                             const float* __restrict__ A,
                             const float* __restrict__ smoothing,
                             float* __restrict__ x2n)
{
    __shared__ float sxk[80*35];   // x_kernel rows, padded stride 35 (34 used)
    __shared__ float sth[34*34];
    __shared__ float sG[16*34];    // theta @ x_f
    __shared__ float ss[80];       // diagonal quadratic forms
    __shared__ float syk[64];      // y_kernel
    __shared__ float sal[16*64];   // alpha logits
    __shared__ float syh[16];
    const int b = blockIdx.x, tid = threadIdx.x;
    for (int i = tid; i < 34*34; i += blockDim.x) sth[i] = theta[i];
    for (int i = tid; i < 80*34; i += blockDim.x) {
        int n = i / 34, o = i - n*34;
        float v = (n < 64) ? x1g[(size_t)(b*64 + n)*36 + o]
                           : x2p[(size_t)(b*16 + (n - 64))*35 + o];
        sxk[n*35 + o] = v;
    }
    if (tid < 64) syk[tid] = xfull[(size_t)(b*64 + tid)*35 + 34];
    __syncthreads();
    if (tid < 80) {
        float s = 0.f;
        for (int o = 0; o < 34; o++) {
            float g = 0.f;
            #pragma unroll 2
            for (int O = 0; O < 34; O++) g = fmaf(sth[o*34 + O], sxk[tid*35 + O], g);
            s = fmaf(g, sxk[tid*35 + o], s);
            if (tid >= 64) sG[(tid - 64)*34 + o] = g;
        }
        ss[tid] = s;
    }
    __syncthreads();
    float sm0 = smoothing[0];
    float sig = 1.f / (1.f + expf(-sm0));
    float scale = -0.5f / (sig * 0.01f);
    for (int i = tid; i < 16*64; i += blockDim.x) {
        int q = i >> 6, p = i & 63;
        float c = 0.f;
        #pragma unroll 2
        for (int o = 0; o < 34; o++) c = fmaf(sG[q*34 + o], sxk[p*35 + o], c);
        float av = scale * (ss[p] + ss[64 + q] - 2.f*c);
        if (A[(64 + q)*80 + p] == 0.f) av = -INFINITY;
        sal[i] = av;
    }
    __syncthreads();
    const int lane = tid & 31, w = tid >> 5;
    for (int q = w; q < 16; q += 4) {
        float a0 = sal[q*64 + lane], a1 = sal[q*64 + 32 + lane];
        float mx = fmaxf(a0, a1);
        #pragma unroll
        for (int off = 16; off; off >>= 1) mx = fmaxf(mx, __shfl_xor_sync(0xffffffffu, mx, off));
        float e0 = expf(a0 - mx), e1 = expf(a1 - mx);
        float se = e0 + e1;
        float sy = e0*syk[lane] + e1*syk[32 + lane];
        #pragma unroll
        for (int off = 16; off; off >>= 1) {
            se += __shfl_xor_sync(0xffffffffu, se, off);
            sy += __shfl_xor_sync(0xffffffffu, sy, off);
        }
        if (lane == 0) syh[q] = sy / se;
    }
    __syncthreads();
    for (int i = tid; i < 16*35; i += blockDim.x) {
        int q = i / 35, c = i - q*35;
        float v = (c < 34) ? sxk[(64 + q)*35 + c] : syh[q];
        x2n[(size_t)(b*16 + q)*35 + c] = v;
    }
}

// ---------------- cd: pairwise distances per batch ------------------------------
__global__ void cd_kernel(const float* __restrict__ x /*stride 35*/,
                          const float* __restrict__ x2n /*stride 35*/,
                          float* __restrict__ cd)
{
    __shared__ float sxa[80*35];
    __shared__ float ssq[80];
    const int b = blockIdx.x, tid = threadIdx.x;
    for (int i = tid; i < 80*35; i += blockDim.x) {
        int n = i / 35, c = i - n*35;
        sxa[i] = (n < 64) ? x[(size_t)(b*64 + n)*35 + c]
                          : x2n[(size_t)(b*16 + (n - 64))*35 + c];
    }
    __syncthreads();
    if (tid < 80) {
        float s = 0.f;
        #pragma unroll 5
        for (int c = 0; c < 35; c++) { float v = sxa[tid*35 + c]; s = fmaf(v, v, s); }
        ssq[tid] = s;
    }
    __syncthreads();
    float* out = cd + (size_t)b*6400;
    for (int i = tid; i < 6400; i += blockDim.x) {
        int r = i / 80, c = i - r*80;
        float dot = 0.f;
        #pragma unroll 5
        for (int k = 0; k < 35; k++) dot = fmaf(sxa[r*35 + k], sxa[c*35 + k], dot);
        float d2 = ssq[r] + ssq[c] - 2.f*dot;
        out[i] = sqrtf(fmaxf(d2, 0.f));
    }
}

// ================================================================================
extern "C" void kernel_launch(void* const* d_in, const int* in_sizes, int n_in,
                              void* d_out, int out_size)
{
    const int*   x1_cat   = (const int*)  d_in[0];
    const float* x1_num   = (const float*)d_in[1];
    const int*   x2_cat   = (const int*)  d_in[2];
    const float* x2_num   = (const float*)d_in[3];
    const int*   e1       = (const int*)  d_in[4];
    const int*   e2       = (const int*)  d_in[5];
    const float* emb0     = (const float*)d_in[6];
    const float* emb1     = (const float*)d_in[7];
    const float* emb2     = (const float*)d_in[8];
    const float* pre_W1   = (const float*)d_in[9];
    const float* pre_b1   = (const float*)d_in[10];
    const float* pre_W2   = (const float*)d_in[11];
    const float* pre_b2   = (const float*)d_in[12];
    const float* pre_W3   = (const float*)d_in[13];
    const float* pre_b3   = (const float*)d_in[14];
    const float* g1_W1    = (const float*)d_in[15];
    const float* g1_b1    = (const float*)d_in[16];
    const float* g1_W2    = (const float*)d_in[17];
    const float* g1_b2    = (const float*)d_in[18];
    const float* g2_W1    = (const float*)d_in[19];
    const float* g2_b1    = (const float*)d_in[20];
    const float* g2_W2    = (const float*)d_in[21];
    const float* g2_b2    = (const float*)d_in[22];
    const float* ker_W    = (const float*)d_in[23];
    const float* smoothing= (const float*)d_in[24];
    const float* Mmat     = (const float*)d_in[25];

    const int n1 = in_sizes[0] / 3;     // 131072
    const int n2 = in_sizes[2] / 3;     // 32768
    const int E1 = in_sizes[4] / 2;     // 1048576
    const int E2 = in_sizes[5] / 2;     // 262144
    const int* e1src = e1, *e1dst = e1 + E1;
    const int* e2src = e2, *e2dst = e2 + E2;

    float* out   = (float*)d_out;
    float* outO  = out;                        // (SB, FUT) = 32768
    float* outCD = out + 32768;                // (SB, 80, 80) = 13107200
    float* outA  = out + 32768 + 13107200;     // (80, 80) = 6400

    float *px, *px2p, *pA, *pB, *pC, *pd1, *pd2, *pth, *px2n;
    cudaGetSymbolAddress((void**)&px,   g_x);
    cudaGetSymbolAddress((void**)&px2p, g_x2p);
    cudaGetSymbolAddress((void**)&pA,   g_bufA);
    cudaGetSymbolAddress((void**)&pB,   g_bufB);
    cudaGetSymbolAddress((void**)&pC,   g_bufC);
    cudaGetSymbolAddress((void**)&pd1,  g_dinv1);
    cudaGetSymbolAddress((void**)&pd2,  g_dinv2);
    cudaGetSymbolAddress((void**)&pth,  g_theta);
    cudaGetSymbolAddress((void**)&px2n, g_x2n);

    // A and theta (tiny)
    a_kernel<<<1, 128>>>(Mmat, outA);
    theta_kernel<<<5, 256>>>(ker_W, pth);

    // pre MLP for x1 and x2
    const int smemPre = (35*128 + 128*128 + 128*34 + 128 + 128 + 48 + 8*128) * 4;
    cudaFuncSetAttribute(pre_kernel, cudaFuncAttributeMaxDynamicSharedMemorySize, smemPre);
    pre_kernel<<<296, 256, smemPre>>>(x1_cat, x1_num, n1,
        pre_W1, pre_b1, pre_W2, pre_b2, pre_W3, pre_b3, emb0, emb1, emb2, px);
    pre_kernel<<<296, 256, smemPre>>>(x2_cat, x2_num, n2,
        pre_W1, pre_b1, pre_W2, pre_b2, pre_W3, pre_b3, emb0, emb1, emb2, px2p);

    // degrees
    deg_init_kernel<<<512, 256>>>(pd1, n1);
    deg_count_kernel<<<(E1 + 255)/256, 256>>>(e1dst, E1, pd1);
    deg_rsqrt_kernel<<<512, 256>>>(pd1, n1);
    deg_init_kernel<<<128, 256>>>(pd2, n2);
    deg_count_kernel<<<(E2 + 255)/256, 256>>>(e2dst, E2, pd2);
    deg_rsqrt_kernel<<<128, 256>>>(pd2, n2);

    // GCN1 layer 1: (n1,35)@(35,64), relu
    gcn_mm_kernel<<<2048, 256>>>(px, 35, 35, g1_W1, 64, pd1, n1, pA, pB, 64);
    edge_kernel<<<(E1 + 255)/256, 256>>>(e1src, e1dst, E1, pd1, pA, pB, 64, 64);
    finalize_kernel<<<8192, 256>>>(pB, g1_b1, pC, n1, 64, 64, 64, 1);
    // GCN1 layer 2: (n1,64)@(64,34) -> x1g (stride 36, 16B-aligned rows)
    gcn_mm_kernel<<<2048, 256>>>(pC, 64, 64, g1_W2, 34, pd1, n1, pA, pB, 36);
    edge_kernel<<<(E1 + 255)/256, 256>>>(e1src, e1dst, E1, pd1, pA, pB, 34, 36);
    finalize_kernel<<<8192, 256>>>(pB, g1_b2, pC, n1, 34, 36, 36, 0);

    // alpha / softmax / yh -> x2new
    alpha_kernel<<<SBK, 128>>>(pC, px2p, px, pth, outA, smoothing, px2n);

    // GCN2 layer 1: (n2,35)@(35,64), relu
    gcn_mm_kernel<<<512, 256>>>(px2n, 35, 35, g2_W1, 64, pd2, n2, pA, pB, 64);
    edge_kernel<<<(E2 + 255)/256, 256>>>(e2src, e2dst, E2, pd2, pA, pB, 64, 64);
    finalize_kernel<<<4096, 256>>>(pB, g2_b1, pC, n2, 64, 64, 64, 1);
    // GCN2 layer 2: (n2,64)@(64,1) -> out
    gcn_mm_kernel<<<512, 256>>>(pC, 64, 64, g2_W2, 1, pd2, n2, pA, pB, 1);
    edge_kernel<<<(E2 + 255)/256, 256>>>(e2src, e2dst, E2, pd2, pA, pB, 1, 1);
    finalize_kernel<<<128, 256>>>(pB, g2_b2, outO, n2, 1, 1, 1, 0);

    // pairwise distances
    cd_kernel<<<SBK, 256>>>(px, px2n, outCD);
}

// round 2
// speedup vs baseline: 2.1645x; 2.1645x over previous
#include <cuda_runtime.h>
#include <math.h>

// Problem constants
#define SBK   2048
#define PASTK 64
#define FUTK  16
#define NK    80
#define N1K   (SBK*PASTK)   // 131072 nodes graph1
#define N2K   (SBK*FUTK)    // 32768 nodes graph2

// ---------------- device scratch (allocation-free rule: __device__ globals) ----
__device__ float g_x[N1K*35];      // pre output for x1 (stride 35)
__device__ float g_x2p[N2K*35];    // pre output for x2 (stride 35)
__device__ float g_bufA[N1K*64];   // h
__device__ float g_bufB[N1K*64];   // agg
__device__ float g_bufC[N1K*64];   // relu/finalized
__device__ float g_dinv1[N1K];
__device__ float g_dinv2[N2K];
__device__ float g_theta[34*34];
__device__ float g_x2n[N2K*35];    // x2 updated (last channel = yh)

// ---------------- vector reductions (sm_90+) ------------------------------------
__device__ __forceinline__ void red_add_v4(float* p, float a, float b, float c, float d)
{
    asm volatile("red.global.add.v4.f32 [%0], {%1, %2, %3, %4};"
                 :: "l"(p), "f"(a), "f"(b), "f"(c), "f"(d) : "memory");
}
__device__ __forceinline__ void red_add_v2(float* p, float a, float b)
{
    asm volatile("red.global.add.v2.f32 [%0], {%1, %2};"
                 :: "l"(p), "f"(a), "f"(b) : "memory");
}

// ---------------- A = softmax(tril-masked relu(M M^T)) -------------------------
__global__ void a_kernel(const float* __restrict__ M, float* __restrict__ A)
{
    __shared__ float sM[80*26];
    int tid = threadIdx.x;
    for (int i = tid; i < 80*26; i += blockDim.x) sM[i] = M[i];
    __syncthreads();
    if (tid < 80) {
        int i = tid;
        float mx = -INFINITY;
        for (int j = 0; j <= i; j++) {
            float s = 0.f;
            #pragma unroll
            for (int k = 0; k < 26; k++) s = fmaf(sM[i*26+k], sM[j*26+k], s);
            s = fmaxf(s, 0.f);
            mx = fmaxf(mx, s);
        }
        float sum = 0.f;
        for (int j = 0; j <= i; j++) {
            float s = 0.f;
            #pragma unroll
            for (int k = 0; k < 26; k++) s = fmaf(sM[i*26+k], sM[j*26+k], s);
            s = fmaxf(s, 0.f);
            float e = expf(s - mx);
            sum += e;
            A[i*80+j] = e;
        }
        float inv = 1.f / sum;
        for (int j = 0; j <= i; j++) A[i*80+j] *= inv;
        for (int j = i+1; j < 80; j++) A[i*80+j] = 0.f;
    }
}

// ---------------- theta = kerW kerW^T -------------------------------------------
__global__ void theta_kernel(const float* __restrict__ kerW, float* __restrict__ th)
{
    int idx = blockIdx.x*blockDim.x + threadIdx.x;
    if (idx < 34*34) {
        int i = idx / 34, j = idx - i*34;
        float s = 0.f;
        #pragma unroll 8
        for (int k = 0; k < 128; k++) s = fmaf(kerW[i*128+k], kerW[j*128+k], s);
        th[idx] = s;
    }
}

// ---------------- pre MLP: 4 rows per warp, hidden layers in registers ----------
__global__ void pre_kernel(const int* __restrict__ cat, const float* __restrict__ num,
                           int nrows,
                           const float* __restrict__ W1, const float* __restrict__ b1,
                           const float* __restrict__ W2, const float* __restrict__ b2,
                           const float* __restrict__ W3, const float* __restrict__ b3,
                           const float* __restrict__ emb0, const float* __restrict__ emb1,
                           const float* __restrict__ emb2, float* __restrict__ out)
{
    extern __shared__ float smem[];
    float* sW1 = smem;               // 35*128
    float* sW2 = sW1 + 35*128;       // 128*128
    float* sW3 = sW2 + 128*128;      // 128*34
    float* sb1 = sW3 + 128*34;       // 128
    float* sb2 = sb1 + 128;          // 128
    float* sb3 = sb2 + 128;          // 48 pad
    int tid = threadIdx.x;
    for (int i = tid; i < 35*128;  i += blockDim.x) sW1[i] = W1[i];
    for (int i = tid; i < 128*128; i += blockDim.x) sW2[i] = W2[i];
    for (int i = tid; i < 128*34;  i += blockDim.x) sW3[i] = W3[i];
    if (tid < 128) { sb1[tid] = b1[tid]; sb2[tid] = b2[tid]; }
    if (tid < 34) sb3[tid] = b3[tid];
    __syncthreads();
    const int lane = tid & 31, warp = tid >> 5, nw = blockDim.x >> 5;
    const unsigned FULL = 0xffffffffu;
    const int rstep = gridDim.x*nw*4;
    for (int r0 = (blockIdx.x*nw + warp)*4; r0 < nrows; r0 += rstep) {
        float oa[4], ob[4];
        #pragma unroll
        for (int j = 0; j < 4; j++) {
            int r = r0 + j;
            int c0 = cat[3*r], c1 = cat[3*r+1], c2 = cat[3*r+2];
            float v;
            if (lane < 16)      v = emb0[c0*16 + lane];
            else if (lane < 24) v = emb1[c1*8 + lane - 16];
            else                v = emb2[c2*8 + lane - 24];
            oa[j] = v;
            ob[j] = (lane < 3) ? num[3*r + lane] : 0.f;
        }
        // ---- layer 1: 35 -> 128 (lane owns cols 4l..4l+3), a[j] = relu out ----
        float4 a[4];
        {
            float4 bias = ((const float4*)sb1)[lane];
            a[0] = bias; a[1] = bias; a[2] = bias; a[3] = bias;
            #pragma unroll
            for (int k = 0; k < 35; k++) {
                float4 w = ((const float4*)(sW1 + k*128))[lane];
                #pragma unroll
                for (int j = 0; j < 4; j++) {
                    float xv = (k < 32) ? __shfl_sync(FULL, oa[j], k)
                                        : __shfl_sync(FULL, ob[j], k - 32);
                    a[j].x = fmaf(xv, w.x, a[j].x); a[j].y = fmaf(xv, w.y, a[j].y);
                    a[j].z = fmaf(xv, w.z, a[j].z); a[j].w = fmaf(xv, w.w, a[j].w);
                }
            }
            #pragma unroll
            for (int j = 0; j < 4; j++) {
                a[j].x = fmaxf(a[j].x,0.f); a[j].y = fmaxf(a[j].y,0.f);
                a[j].z = fmaxf(a[j].z,0.f); a[j].w = fmaxf(a[j].w,0.f);
            }
        }
        // ---- layer 2: 128 -> 128, h broadcast from registers via shuffle ----
        float4 bb[4];
        {
            float4 bias = ((const float4*)sb2)[lane];
            bb[0] = bias; bb[1] = bias; bb[2] = bias; bb[3] = bias;
            #pragma unroll
            for (int k = 0; k < 128; k++) {
                float4 w = ((const float4*)(sW2 + k*128))[lane];
                const int srcl = k >> 2;
                #pragma unroll
                for (int j = 0; j < 4; j++) {
                    float comp = ((k & 3) == 0) ? a[j].x : ((k & 3) == 1) ? a[j].y
                               : ((k & 3) == 2) ? a[j].z : a[j].w;
                    float hv = __shfl_sync(FULL, comp, srcl);
                    bb[j].x = fmaf(hv, w.x, bb[j].x); bb[j].y = fmaf(hv, w.y, bb[j].y);
                    bb[j].z = fmaf(hv, w.z, bb[j].z); bb[j].w = fmaf(hv, w.w, bb[j].w);
                }
            }
            #pragma unroll
            for (int j = 0; j < 4; j++) {
                bb[j].x = fmaxf(bb[j].x,0.f); bb[j].y = fmaxf(bb[j].y,0.f);
                bb[j].z = fmaxf(bb[j].z,0.f); bb[j].w = fmaxf(bb[j].w,0.f);
            }
        }
        // ---- layer 3: 128 -> 34 ----
        {
            const int j0 = lane, j1 = lane + 32;
            const bool has1 = (j1 < 34);
            float acc0[4] = {0,0,0,0}, acc1[4] = {0,0,0,0};
            #pragma unroll
            for (int k = 0; k < 128; k++) {
                float w0 = sW3[k*34 + j0];
                float w1 = has1 ? sW3[k*34 + j1] : 0.f;
                const int srcl = k >> 2;
                #pragma unroll
                for (int j = 0; j < 4; j++) {
                    float comp = ((k & 3) == 0) ? bb[j].x : ((k & 3) == 1) ? bb[j].y
                               : ((k & 3) == 2) ? bb[j].z : bb[j].w;
                    float hv = __shfl_sync(FULL, comp, srcl);
                    acc0[j] = fmaf(hv, w0, acc0[j]);
                    acc1[j] = fmaf(hv, w1, acc1[j]);
                }
            }
            #pragma unroll
            for (int j = 0; j < 4; j++) {
                float n2v = __shfl_sync(FULL, ob[j], 2);
                float* orow = out + (size_t)(r0 + j)*35;
                orow[j0] = acc0[j] + sb3[j0];
                if (has1) orow[j1] = acc1[j] + sb3[j1];
                if (lane == 0) orow[34] = n2v;
            }
        }
    }
}

// ---------------- degree kernels ----------------------------------------------
__global__ void deg_init_kernel(float* __restrict__ d, int n)
{
    for (int i = blockIdx.x*blockDim.x + threadIdx.x; i < n; i += gridDim.x*blockDim.x)
        d[i] = 1.0f;
}
__global__ void deg_count_kernel(const int* __restrict__ dst, int E, float* __restrict__ d)
{
    int e = blockIdx.x*blockDim.x + threadIdx.x;
    if (e < E) atomicAdd(&d[dst[e]], 1.0f);
}
__global__ void deg_rsqrt_kernel(float* __restrict__ d, int n)
{
    for (int i = blockIdx.x*blockDim.x + threadIdx.x; i < n; i += gridDim.x*blockDim.x)
        d[i] = rsqrtf(d[i]);
}

// ---------------- GCN linear: h = x@W, agg init = h * dinv^2; 4 rows/warp ------
__global__ void gcn_mm_kernel(const float* __restrict__ x, int strideIn, int din,
                              const float* __restrict__ W, int dout,
                              const float* __restrict__ dinv, int n,
                              float* __restrict__ h, float* __restrict__ agg, int strideOut)
{
    __shared__ float sW[64*64];
    int tid = threadIdx.x;
    for (int i = tid; i < din*dout; i += blockDim.x) sW[i] = W[i];
    __syncthreads();
    const int lane = tid & 31, warp = tid >> 5, nw = blockDim.x >> 5;
    const unsigned FULL = 0xffffffffu;
    if (dout == 1) {
        for (int r = blockIdx.x*nw + warp; r < n; r += gridDim.x*nw) {
            const float* xr = x + (size_t)r*strideIn;
            float xa = (lane < din)      ? xr[lane]      : 0.f;
            float xb = (lane + 32 < din) ? xr[lane + 32] : 0.f;
            float di = dinv[r]; float d2 = di*di;
            float s = xa * sW[lane];
            if (lane + 32 < din) s = fmaf(xb, sW[lane+32], s);
            #pragma unroll
            for (int off = 16; off; off >>= 1) s += __shfl_xor_sync(FULL, s, off);
            if (lane == 0) { h[r] = s; agg[r] = s*d2; }
        }
        return;
    }
    const int rstep = gridDim.x*nw*4;
    for (int r0 = (blockIdx.x*nw + warp)*4; r0 < n; r0 += rstep) {
        float xa[4], xb[4], d2[4];
        #pragma unroll
        for (int j = 0; j < 4; j++) {
            const float* xr = x + (size_t)(r0 + j)*strideIn;
            xa[j] = (lane < din)      ? xr[lane]      : 0.f;
            xb[j] = (lane + 32 < din) ? xr[lane + 32] : 0.f;
            float di = dinv[r0 + j]; d2[j] = di*di;
        }
        const int j0 = lane, j1 = lane + 32;
        const bool has1 = (j1 < dout);
        float acc0[4] = {0,0,0,0}, acc1[4] = {0,0,0,0};
        for (int k = 0; k < din; k++) {
            float w0 = sW[k*dout + j0];
            float w1 = has1 ? sW[k*dout + j1] : 0.f;
            #pragma unroll
            for (int j = 0; j < 4; j++) {
                float xv = (k < 32) ? __shfl_sync(FULL, xa[j], k)
                                    : __shfl_sync(FULL, xb[j], k - 32);
                acc0[j] = fmaf(xv, w0, acc0[j]);
                acc1[j] = fmaf(xv, w1, acc1[j]);
            }
        }
        #pragma unroll
        for (int j = 0; j < 4; j++) {
            float* hr = h   + (size_t)(r0 + j)*strideOut;
            float* ar = agg + (size_t)(r0 + j)*strideOut;
            hr[j0] = acc0[j]; ar[j0] = acc0[j]*d2[j];
            if (has1) { hr[j1] = acc1[j]; ar[j1] = acc1[j]*d2[j]; }
        }
    }
}

// ---------------- edge scatter: 8 threads per edge, vectorized red -------------
// dout must be 64 or 34 here.
__global__ void edge_kernel_vec(const int* __restrict__ src, const int* __restrict__ dst, int E,
                                const float* __restrict__ dinv, const float* __restrict__ h,
                                float* __restrict__ agg, int dout, int stride)
{
    int gid = blockIdx.x*blockDim.x + threadIdx.x;
    int e = gid >> 3, sub = gid & 7;
    if (e >= E) return;
    int s = src[e], d = dst[e];
    float coef = dinv[s]*dinv[d];
    const float* hp = h   + (size_t)s*stride;
    float*       ap = agg + (size_t)d*stride;
    float4 v = __ldg((const float4*)(hp + sub*4));
    red_add_v4(ap + sub*4, v.x*coef, v.y*coef, v.z*coef, v.w*coef);
    if (dout == 64) {
        float4 u = __ldg((const float4*)(hp + 32 + sub*4));
        red_add_v4(ap + 32 + sub*4, u.x*coef, u.y*coef, u.z*coef, u.w*coef);
    } else if (sub == 0) { // dout == 34, tail channels 32..33
        float2 u = __ldg((const float2*)(hp + 32));
        red_add_v2(ap + 32, u.x*coef, u.y*coef);
    }
}

// dout == 1 path
__global__ void edge_kernel_1(const int* __restrict__ src, const int* __restrict__ dst, int E,
                              const float* __restrict__ dinv, const float* __restrict__ h,
                              float* __restrict__ agg)
{
    int e = blockIdx.x*blockDim.x + threadIdx.x;
    if (e >= E) return;
    int s = src[e], d = dst[e];
    atomicAdd(&agg[d], h[s]*dinv[s]*dinv[d]);
}

// ---------------- finalize: y = (agg + b) [relu] --------------------------------
__global__ void finalize_kernel(const float* __restrict__ agg, const float* __restrict__ b,
                                float* __restrict__ y, int n, int dout,
                                int strideIn, int strideOut, int doRelu)
{
    int total = n*dout;
    for (int idx = blockIdx.x*blockDim.x + threadIdx.x; idx < total; idx += gridDim.x*blockDim.x) {
        int r = idx / dout, c = idx - r*dout;
        float v = agg[(size_t)r*strideIn + c] + b[c];
        if (doRelu) v = fmaxf(v, 0.f);
        y[(size_t)r*strideOut + c] = v;
    }
}

// ---------------- alpha / softmax / yh / build x2new ---------------------------
__global__ void alpha_kernel(const float* __restrict__ x1g /*stride 36*/,
                             const float* __restrict__ x2p /*stride 35*/,
                             const float* __restrict__ xfull /*stride 35*/,
                             const float* __restrict__ theta,
                             const float* __restrict__ A,
                             const float* __restrict__ smoothing,
                             float* __restrict__ x2n)
{
    __shared__ float sxk[80*35];
    __shared__ float sth[34*34];
    __shared__ float sG[16*34];
    __shared__ float ss[80];
    __shared__ float syk[64];
    __shared__ float sal[16*64];
    __shared__ float syh[16];
    const int b = blockIdx.x, tid = threadIdx.x;
    for (int i = tid; i < 34*34; i += blockDim.x) sth[i] = theta[i];
    for (int i = tid; i < 80*34; i += blockDim.x) {
        int n = i / 34, o = i - n*34;
        float v = (n < 64) ? x1g[(size_t)(b*64 + n)*36 + o]
                           : x2p[(size_t)(b*16 + (n - 64))*35 + o];
        sxk[n*35 + o] = v;
    }
    if (tid < 64) syk[tid] = xfull[(size_t)(b*64 + tid)*35 + 34];
    __syncthreads();
    if (tid < 80) {
        float s = 0.f;
        for (int o = 0; o < 34; o++) {
            float g = 0.f;
            #pragma unroll 2
            for (int O = 0; O < 34; O++) g = fmaf(sth[o*34 + O], sxk[tid*35 + O], g);
            s = fmaf(g, sxk[tid*35 + o], s);
            if (tid >= 64) sG[(tid - 64)*34 + o] = g;
        }
        ss[tid] = s;
    }
    __syncthreads();
    float sm0 = smoothing[0];
    float sig = 1.f / (1.f + expf(-sm0));
    float scale = -0.5f / (sig * 0.01f);
    for (int i = tid; i < 16*64; i += blockDim.x) {
        int q = i >> 6, p = i & 63;
        float c = 0.f;
        #pragma unroll 2
        for (int o = 0; o < 34; o++) c = fmaf(sG[q*34 + o], sxk[p*35 + o], c);
        float av = scale * (ss[p] + ss[64 + q] - 2.f*c);
        if (A[(64 + q)*80 + p] == 0.f) av = -INFINITY;
        sal[i] = av;
    }
    __syncthreads();
    const int lane = tid & 31, w = tid >> 5;
    for (int q = w; q < 16; q += 4) {
        float a0 = sal[q*64 + lane], a1 = sal[q*64 + 32 + lane];
        float mx = fmaxf(a0, a1);
        #pragma unroll
        for (int off = 16; off; off >>= 1) mx = fmaxf(mx, __shfl_xor_sync(0xffffffffu, mx, off));
        float e0 = expf(a0 - mx), e1 = expf(a1 - mx);
        float se = e0 + e1;
        float sy = e0*syk[lane] + e1*syk[32 + lane];
        #pragma unroll
        for (int off = 16; off; off >>= 1) {
            se += __shfl_xor_sync(0xffffffffu, se, off);
            sy += __shfl_xor_sync(0xffffffffu, sy, off);
        }
        if (lane == 0) syh[q] = sy / se;
    }
    __syncthreads();
    for (int i = tid; i < 16*35; i += blockDim.x) {
        int q = i / 35, c = i - q*35;
        float v = (c < 34) ? sxk[(64 + q)*35 + c] : syh[q];
        x2n[(size_t)(b*16 + q)*35 + c] = v;
    }
}

// ---------------- cd: pairwise distances, 5x5 register tile per thread ----------
__global__ void cd_kernel(const float* __restrict__ x /*stride 35*/,
                          const float* __restrict__ x2n /*stride 35*/,
                          float* __restrict__ cd)
{
    __shared__ float sxa[80*35];
    __shared__ float ssq[80];
    const int b = blockIdx.x, tid = threadIdx.x;
    for (int i = tid; i < 80*35; i += blockDim.x) {
        int n = i / 35, c = i - n*35;
        sxa[i] = (n < 64) ? x[(size_t)(b*64 + n)*35 + c]
                          : x2n[(size_t)(b*16 + (n - 64))*35 + c];
    }
    __syncthreads();
    if (tid < 80) {
        float s = 0.f;
        #pragma unroll 5
        for (int c = 0; c < 35; c++) { float v = sxa[tid*35 + c]; s = fmaf(v, v, s); }
        ssq[tid] = s;
    }
    __syncthreads();
    // 256 threads: tr = tid/16 (0..15), tc = tid%16. r = tr + 16*i, c = tc + 16*j.
    const int tr = tid >> 4, tc = tid & 15;
    float acc[5][5];
    #pragma unroll
    for (int i = 0; i < 5; i++)
        #pragma unroll
        for (int j = 0; j < 5; j++) acc[i][j] = 0.f;
    for (int k = 0; k < 35; k++) {
        float rv[5], cv[5];
        #pragma unroll
        for (int i = 0; i < 5; i++) rv[i] = sxa[(tr + 16*i)*35 + k];
        #pragma unroll
        for (int j = 0; j < 5; j++) cv[j] = sxa[(tc + 16*j)*35 + k];
        #pragma unroll
        for (int i = 0; i < 5; i++)
            #pragma unroll
            for (int j = 0; j < 5; j++) acc[i][j] = fmaf(rv[i], cv[j], acc[i][j]);
    }
    float* out = cd + (size_t)b*6400;
    #pragma unroll
    for (int i = 0; i < 5; i++) {
        int r = tr + 16*i;
        float sr = ssq[r];
        #pragma unroll
        for (int j = 0; j < 5; j++) {
            int c = tc + 16*j;
            float d2 = sr + ssq[c] - 2.f*acc[i][j];
            out[r*80 + c] = sqrtf(fmaxf(d2, 0.f));
        }
    }
}

// ================================================================================
extern "C" void kernel_launch(void* const* d_in, const int* in_sizes, int n_in,
                              void* d_out, int out_size)
{
    const int*   x1_cat   = (const int*)  d_in[0];
    const float* x1_num   = (const float*)d_in[1];
    const int*   x2_cat   = (const int*)  d_in[2];
    const float* x2_num   = (const float*)d_in[3];
    const int*   e1       = (const int*)  d_in[4];
    const int*   e2       = (const int*)  d_in[5];
    const float* emb0     = (const float*)d_in[6];
    const float* emb1     = (const float*)d_in[7];
    const float* emb2     = (const float*)d_in[8];
    const float* pre_W1   = (const float*)d_in[9];
    const float* pre_b1   = (const float*)d_in[10];
    const float* pre_W2   = (const float*)d_in[11];
    const float* pre_b2   = (const float*)d_in[12];
    const float* pre_W3   = (const float*)d_in[13];
    const float* pre_b3   = (const float*)d_in[14];
    const float* g1_W1    = (const float*)d_in[15];
    const float* g1_b1    = (const float*)d_in[16];
    const float* g1_W2    = (const float*)d_in[17];
    const float* g1_b2    = (const float*)d_in[18];
    const float* g2_W1    = (const float*)d_in[19];
    const float* g2_b1    = (const float*)d_in[20];
    const float* g2_W2    = (const float*)d_in[21];
    const float* g2_b2    = (const float*)d_in[22];
    const float* ker_W    = (const float*)d_in[23];
    const float* smoothing= (const float*)d_in[24];
    const float* Mmat     = (const float*)d_in[25];

    const int n1 = in_sizes[0] / 3;     // 131072
    const int n2 = in_sizes[2] / 3;     // 32768
    const int E1 = in_sizes[4] / 2;     // 1048576
    const int E2 = in_sizes[5] / 2;     // 262144
    const int* e1src = e1, *e1dst = e1 + E1;
    const int* e2src = e2, *e2dst = e2 + E2;

    float* out   = (float*)d_out;
    float* outO  = out;                        // (SB, FUT) = 32768
    float* outCD = out + 32768;                // (SB, 80, 80) = 13107200
    float* outA  = out + 32768 + 13107200;     // (80, 80) = 6400

    float *px, *px2p, *pA, *pB, *pC, *pd1, *pd2, *pth, *px2n;
    cudaGetSymbolAddress((void**)&px,   g_x);
    cudaGetSymbolAddress((void**)&px2p, g_x2p);
    cudaGetSymbolAddress((void**)&pA,   g_bufA);
    cudaGetSymbolAddress((void**)&pB,   g_bufB);
    cudaGetSymbolAddress((void**)&pC,   g_bufC);
    cudaGetSymbolAddress((void**)&pd1,  g_dinv1);
    cudaGetSymbolAddress((void**)&pd2,  g_dinv2);
    cudaGetSymbolAddress((void**)&pth,  g_theta);
    cudaGetSymbolAddress((void**)&px2n, g_x2n);

    // A and theta (tiny)
    a_kernel<<<1, 128>>>(Mmat, outA);
    theta_kernel<<<5, 256>>>(ker_W, pth);

    // pre MLP for x1 and x2
    const int smemPre = (35*128 + 128*128 + 128*34 + 128 + 128 + 48) * 4;
    cudaFuncSetAttribute(pre_kernel, cudaFuncAttributeMaxDynamicSharedMemorySize, smemPre);
    pre_kernel<<<296, 256, smemPre>>>(x1_cat, x1_num, n1,
        pre_W1, pre_b1, pre_W2, pre_b2, pre_W3, pre_b3, emb0, emb1, emb2, px);
    pre_kernel<<<296, 256, smemPre>>>(x2_cat, x2_num, n2,
        pre_W1, pre_b1, pre_W2, pre_b2, pre_W3, pre_b3, emb0, emb1, emb2, px2p);

    // degrees
    deg_init_kernel<<<512, 256>>>(pd1, n1);
    deg_count_kernel<<<(E1 + 255)/256, 256>>>(e1dst, E1, pd1);
    deg_rsqrt_kernel<<<512, 256>>>(pd1, n1);
    deg_init_kernel<<<128, 256>>>(pd2, n2);
    deg_count_kernel<<<(E2 + 255)/256, 256>>>(e2dst, E2, pd2);
    deg_rsqrt_kernel<<<128, 256>>>(pd2, n2);

    // GCN1 layer 1: (n1,35)@(35,64), relu
    gcn_mm_kernel<<<2048, 256>>>(px, 35, 35, g1_W1, 64, pd1, n1, pA, pB, 64);
    edge_kernel_vec<<<(E1*8 + 255)/256, 256>>>(e1src, e1dst, E1, pd1, pA, pB, 64, 64);
    finalize_kernel<<<8192, 256>>>(pB, g1_b1, pC, n1, 64, 64, 64, 1);
    // GCN1 layer 2: (n1,64)@(64,34) -> stride 36
    gcn_mm_kernel<<<2048, 256>>>(pC, 64, 64, g1_W2, 34, pd1, n1, pA, pB, 36);
    edge_kernel_vec<<<(E1*8 + 255)/256, 256>>>(e1src, e1dst, E1, pd1, pA, pB, 34, 36);
    finalize_kernel<<<8192, 256>>>(pB, g1_b2, pC, n1, 34, 36, 36, 0);

    // alpha / softmax / yh -> x2new
    alpha_kernel<<<SBK, 128>>>(pC, px2p, px, pth, outA, smoothing, px2n);

    // GCN2 layer 1: (n2,35)@(35,64), relu
    gcn_mm_kernel<<<512, 256>>>(px2n, 35, 35, g2_W1, 64, pd2, n2, pA, pB, 64);
    edge_kernel_vec<<<(E2*8 + 255)/256, 256>>>(e2src, e2dst, E2, pd2, pA, pB, 64, 64);
    finalize_kernel<<<4096, 256>>>(pB, g2_b1, pC, n2, 64, 64, 64, 1);
    // GCN2 layer 2: (n2,64)@(64,1) -> out
    gcn_mm_kernel<<<512, 256>>>(pC, 64, 64, g2_W2, 1, pd2, n2, pA, pB, 1);
    edge_kernel_1<<<(E2 + 255)/256, 256>>>(e2src, e2dst, E2, pd2, pA, pB);
    finalize_kernel<<<128, 256>>>(pB, g2_b2, outO, n2, 1, 1, 1, 0);

    // pairwise distances
    cd_kernel<<<SBK, 256>>>(px, px2n, outCD);
}

// round 3
// speedup vs baseline: 2.2294x; 1.0300x over previous
#include <cuda_runtime.h>
#include <math.h>

// Problem constants
#define SBK   2048
#define PASTK 64
#define FUTK  16
#define N1K   (SBK*PASTK)   // 131072 nodes graph1
#define N2K   (SBK*FUTK)    // 32768 nodes graph2
#define E1K   (N1K*8)       // 1048576
#define E2K   (N2K*8)       // 262144

// ---------------- device scratch (allocation-free rule: __device__ globals) ----
__device__ float g_x[N1K*35];      // pre output for x1 (stride 35)
__device__ float g_x2p[N2K*35];    // pre output for x2 (stride 35)
__device__ float g_bufA[N1K*64];   // h
__device__ float g_bufB[N1K*64];   // h (second)
__device__ float g_bufC[N1K*64];   // activations
__device__ float g_dinv1[N1K];
__device__ float g_dinv2[N2K];
__device__ float g_theta[34*34];
__device__ float g_x2n[N2K*35];    // x2 updated (last channel = yh)
// CSR scratch
__device__ int g_counts1[N1K];
__device__ int g_rowptr1[N1K];
__device__ int g_cursor1[N1K];
__device__ int g_eidx1[E1K];
__device__ int g_counts2[N2K];
__device__ int g_rowptr2[N2K];
__device__ int g_cursor2[N2K];
__device__ int g_eidx2[E2K];
__device__ int g_partials[64];

// ---------------- A = softmax(tril-masked relu(M M^T)) -------------------------
__global__ void a_kernel(const float* __restrict__ M, float* __restrict__ A)
{
    __shared__ float sM[80*26];
    int tid = threadIdx.x;
    for (int i = tid; i < 80*26; i += blockDim.x) sM[i] = M[i];
    __syncthreads();
    if (tid < 80) {
        int i = tid;
        float mx = -INFINITY;
        for (int j = 0; j <= i; j++) {
            float s = 0.f;
            #pragma unroll
            for (int k = 0; k < 26; k++) s = fmaf(sM[i*26+k], sM[j*26+k], s);
            s = fmaxf(s, 0.f);
            mx = fmaxf(mx, s);
        }
        float sum = 0.f;
        for (int j = 0; j <= i; j++) {
            float s = 0.f;
            #pragma unroll
            for (int k = 0; k < 26; k++) s = fmaf(sM[i*26+k], sM[j*26+k], s);
            s = fmaxf(s, 0.f);
            float e = expf(s - mx);
            sum += e;
            A[i*80+j] = e;
        }
        float inv = 1.f / sum;
        for (int j = 0; j <= i; j++) A[i*80+j] *= inv;
        for (int j = i+1; j < 80; j++) A[i*80+j] = 0.f;
    }
}

// ---------------- theta = kerW kerW^T -------------------------------------------
__global__ void theta_kernel(const float* __restrict__ kerW, float* __restrict__ th)
{
    int idx = blockIdx.x*blockDim.x + threadIdx.x;
    if (idx < 34*34) {
        int i = idx / 34, j = idx - i*34;
        float s = 0.f;
        #pragma unroll 8
        for (int k = 0; k < 128; k++) s = fmaf(kerW[i*128+k], kerW[j*128+k], s);
        th[idx] = s;
    }
}

// ---------------- pre MLP: 4 rows per warp, hidden layers in registers ----------
__global__ void pre_kernel(const int* __restrict__ cat, const float* __restrict__ num,
                           int nrows,
                           const float* __restrict__ W1, const float* __restrict__ b1,
                           const float* __restrict__ W2, const float* __restrict__ b2,
                           const float* __restrict__ W3, const float* __restrict__ b3,
                           const float* __restrict__ emb0, const float* __restrict__ emb1,
                           const float* __restrict__ emb2, float* __restrict__ out)
{
    extern __shared__ float smem[];
    float* sW1 = smem;               // 35*128
    float* sW2 = sW1 + 35*128;       // 128*128
    float* sW3 = sW2 + 128*128;      // 128*34
    float* sb1 = sW3 + 128*34;       // 128
    float* sb2 = sb1 + 128;          // 128
    float* sb3 = sb2 + 128;          // 48 pad
    int tid = threadIdx.x;
    for (int i = tid; i < 35*128;  i += blockDim.x) sW1[i] = W1[i];
    for (int i = tid; i < 128*128; i += blockDim.x) sW2[i] = W2[i];
    for (int i = tid; i < 128*34;  i += blockDim.x) sW3[i] = W3[i];
    if (tid < 128) { sb1[tid] = b1[tid]; sb2[tid] = b2[tid]; }
    if (tid < 34) sb3[tid] = b3[tid];
    __syncthreads();
    const int lane = tid & 31, warp = tid >> 5, nw = blockDim.x >> 5;
    const unsigned FULL = 0xffffffffu;
    const int rstep = gridDim.x*nw*4;
    for (int r0 = (blockIdx.x*nw + warp)*4; r0 < nrows; r0 += rstep) {
        float oa[4], ob[4];
        #pragma unroll
        for (int j = 0; j < 4; j++) {
            int r = r0 + j;
            int c0 = cat[3*r], c1 = cat[3*r+1], c2 = cat[3*r+2];
            float v;
            if (lane < 16)      v = emb0[c0*16 + lane];
            else if (lane < 24) v = emb1[c1*8 + lane - 16];
            else                v = emb2[c2*8 + lane - 24];
            oa[j] = v;
            ob[j] = (lane < 3) ? num[3*r + lane] : 0.f;
        }
        float4 a[4];
        {
            float4 bias = ((const float4*)sb1)[lane];
            a[0] = bias; a[1] = bias; a[2] = bias; a[3] = bias;
            #pragma unroll
            for (int k = 0; k < 35; k++) {
                float4 w = ((const float4*)(sW1 + k*128))[lane];
                #pragma unroll
                for (int j = 0; j < 4; j++) {
                    float xv = (k < 32) ? __shfl_sync(FULL, oa[j], k)
                                        : __shfl_sync(FULL, ob[j], k - 32);
                    a[j].x = fmaf(xv, w.x, a[j].x); a[j].y = fmaf(xv, w.y, a[j].y);
                    a[j].z = fmaf(xv, w.z, a[j].z); a[j].w = fmaf(xv, w.w, a[j].w);
                }
            }
            #pragma unroll
            for (int j = 0; j < 4; j++) {
                a[j].x = fmaxf(a[j].x,0.f); a[j].y = fmaxf(a[j].y,0.f);
                a[j].z = fmaxf(a[j].z,0.f); a[j].w = fmaxf(a[j].w,0.f);
            }
        }
        float4 bb[4];
        {
            float4 bias = ((const float4*)sb2)[lane];
            bb[0] = bias; bb[1] = bias; bb[2] = bias; bb[3] = bias;
            #pragma unroll
            for (int k = 0; k < 128; k++) {
                float4 w = ((const float4*)(sW2 + k*128))[lane];
                const int srcl = k >> 2;
                #pragma unroll
                for (int j = 0; j < 4; j++) {
                    float comp = ((k & 3) == 0) ? a[j].x : ((k & 3) == 1) ? a[j].y
                               : ((k & 3) == 2) ? a[j].z : a[j].w;
                    float hv = __shfl_sync(FULL, comp, srcl);
                    bb[j].x = fmaf(hv, w.x, bb[j].x); bb[j].y = fmaf(hv, w.y, bb[j].y);
                    bb[j].z = fmaf(hv, w.z, bb[j].z); bb[j].w = fmaf(hv, w.w, bb[j].w);
                }
            }
            #pragma unroll
            for (int j = 0; j < 4; j++) {
                bb[j].x = fmaxf(bb[j].x,0.f); bb[j].y = fmaxf(bb[j].y,0.f);
                bb[j].z = fmaxf(bb[j].z,0.f); bb[j].w = fmaxf(bb[j].w,0.f);
            }
        }
        {
            const int j0 = lane, j1 = lane + 32;
            const bool has1 = (j1 < 34);
            float acc0[4] = {0,0,0,0}, acc1[4] = {0,0,0,0};
            #pragma unroll
            for (int k = 0; k < 128; k++) {
                float w0 = sW3[k*34 + j0];
                float w1 = has1 ? sW3[k*34 + j1] : 0.f;
                const int srcl = k >> 2;
                #pragma unroll
                for (int j = 0; j < 4; j++) {
                    float comp = ((k & 3) == 0) ? bb[j].x : ((k & 3) == 1) ? bb[j].y
                               : ((k & 3) == 2) ? bb[j].z : bb[j].w;
                    float hv = __shfl_sync(FULL, comp, srcl);
                    acc0[j] = fmaf(hv, w0, acc0[j]);
                    acc1[j] = fmaf(hv, w1, acc1[j]);
                }
            }
            #pragma unroll
            for (int j = 0; j < 4; j++) {
                float n2v = __shfl_sync(FULL, ob[j], 2);
                float* orow = out + (size_t)(r0 + j)*35;
                orow[j0] = acc0[j] + sb3[j0];
                if (has1) orow[j1] = acc1[j] + sb3[j1];
                if (lane == 0) orow[34] = n2v;
            }
        }
    }
}

// ---------------- CSR build -----------------------------------------------------
__global__ void zero_int_kernel(int* __restrict__ p, int n)
{
    for (int i = blockIdx.x*blockDim.x + threadIdx.x; i < n; i += gridDim.x*blockDim.x)
        p[i] = 0;
}
__global__ void count_kernel(const int* __restrict__ dst, int E, int* __restrict__ counts)
{
    int e = blockIdx.x*blockDim.x + threadIdx.x;
    if (e < E) atomicAdd(&counts[dst[e]], 1);
}
// block-level scan: 1024 threads x 4 elems = 4096 per block
__global__ void scan1_kernel(const int* __restrict__ in, int* __restrict__ out,
                             int* __restrict__ partials, int n)
{
    __shared__ int sdata[1024];
    int tid = threadIdx.x;
    int base = blockIdx.x*4096 + tid*4;
    int v[4];
    #pragma unroll
    for (int j = 0; j < 4; j++) v[j] = (base + j < n) ? in[base + j] : 0;
    int tsum = v[0] + v[1] + v[2] + v[3];
    sdata[tid] = tsum;
    __syncthreads();
    for (int off = 1; off < 1024; off <<= 1) {
        int add = (tid >= off) ? sdata[tid - off] : 0;
        __syncthreads();
        sdata[tid] += add;
        __syncthreads();
    }
    int run = sdata[tid] - tsum;   // exclusive prefix of this thread
    #pragma unroll
    for (int j = 0; j < 4; j++) {
        if (base + j < n) out[base + j] = run;
        run += v[j];
    }
    if (tid == 1023) partials[blockIdx.x] = sdata[1023];
}
__global__ void scan2_kernel(int* __restrict__ partials, int B)
{
    __shared__ int sdata[1024];
    int tid = threadIdx.x;
    int v = (tid < B) ? partials[tid] : 0;
    sdata[tid] = v;
    __syncthreads();
    for (int off = 1; off < 1024; off <<= 1) {
        int add = (tid >= off) ? sdata[tid - off] : 0;
        __syncthreads();
        sdata[tid] += add;
        __syncthreads();
    }
    if (tid < B) partials[tid] = sdata[tid] - v; // exclusive
}
__global__ void scan3_kernel(int* __restrict__ rowptr, const int* __restrict__ partials,
                             const int* __restrict__ counts, int* __restrict__ cursor,
                             float* __restrict__ dinv, int n)
{
    int i = blockIdx.x*blockDim.x + threadIdx.x;
    if (i < n) {
        int rp = rowptr[i] + partials[i >> 12];
        rowptr[i] = rp;
        cursor[i] = rp;
        dinv[i] = rsqrtf(1.0f + (float)counts[i]);
    }
}
__global__ void scatter_kernel(const int* __restrict__ src, const int* __restrict__ dst,
                               int E, int* __restrict__ cursor, int* __restrict__ eidx)
{
    int e = blockIdx.x*blockDim.x + threadIdx.x;
    if (e < E) {
        int pos = atomicAdd(&cursor[dst[e]], 1);
        eidx[pos] = src[e];
    }
}

// ---------------- GCN linear: h = x@W; 4 rows/warp ------------------------------
__global__ void gcn_mm_kernel(const float* __restrict__ x, int strideIn, int din,
                              const float* __restrict__ W, int dout, int n,
                              float* __restrict__ h, int strideOut)
{
    __shared__ float sW[64*64];
    int tid = threadIdx.x;
    for (int i = tid; i < din*dout; i += blockDim.x) sW[i] = W[i];
    __syncthreads();
    const int lane = tid & 31, warp = tid >> 5, nw = blockDim.x >> 5;
    const unsigned FULL = 0xffffffffu;
    if (dout == 1) {
        for (int r = blockIdx.x*nw + warp; r < n; r += gridDim.x*nw) {
            const float* xr = x + (size_t)r*strideIn;
            float xa = (lane < din)      ? xr[lane]      : 0.f;
            float xb = (lane + 32 < din) ? xr[lane + 32] : 0.f;
            float s = xa * sW[lane];
            if (lane + 32 < din) s = fmaf(xb, sW[lane+32], s);
            #pragma unroll
            for (int off = 16; off; off >>= 1) s += __shfl_xor_sync(FULL, s, off);
            if (lane == 0) h[r] = s;
        }
        return;
    }
    const int rstep = gridDim.x*nw*4;
    for (int r0 = (blockIdx.x*nw + warp)*4; r0 < n; r0 += rstep) {
        float xa[4], xb[4];
        #pragma unroll
        for (int j = 0; j < 4; j++) {
            const float* xr = x + (size_t)(r0 + j)*strideIn;
            xa[j] = (lane < din)      ? xr[lane]      : 0.f;
            xb[j] = (lane + 32 < din) ? xr[lane + 32] : 0.f;
        }
        const int j0 = lane, j1 = lane + 32;
        const bool has1 = (j1 < dout);
        float acc0[4] = {0,0,0,0}, acc1[4] = {0,0,0,0};
        for (int k = 0; k < din; k++) {
            float w0 = sW[k*dout + j0];
            float w1 = has1 ? sW[k*dout + j1] : 0.f;
            #pragma unroll
            for (int j = 0; j < 4; j++) {
                float xv = (k < 32) ? __shfl_sync(FULL, xa[j], k)
                                    : __shfl_sync(FULL, xb[j], k - 32);
                acc0[j] = fmaf(xv, w0, acc0[j]);
                acc1[j] = fmaf(xv, w1, acc1[j]);
            }
        }
        #pragma unroll
        for (int j = 0; j < 4; j++) {
            float* hr = h + (size_t)(r0 + j)*strideOut;
            hr[j0] = acc0[j];
            if (has1) hr[j1] = acc1[j];
        }
    }
}

// ---------------- GCN gather: out[d] = [relu](sum coef*h[s] + d2*h[d] + b) ------
// warp per node; dout in {34, 64}
__global__ void gather_kernel(const float* __restrict__ h, int stride, int dout,
                              const int* __restrict__ rowptr, const int* __restrict__ counts,
                              const int* __restrict__ eidx, const float* __restrict__ dinv,
                              const float* __restrict__ bias, float* __restrict__ out,
                              int outStride, int n, int doRelu)
{
    int gw = (blockIdx.x*blockDim.x + threadIdx.x) >> 5;
    int lane = threadIdx.x & 31;
    if (gw >= n) return;
    const int r = gw;
    const int j0 = lane, j1 = lane + 32;
    const bool has1 = (j1 < dout);
    float dr = dinv[r];
    float d2 = dr*dr;
    const float* hr = h + (size_t)r*stride;
    float acc0 = hr[j0]*d2;
    float acc1 = has1 ? hr[j1]*d2 : 0.f;
    int start = rowptr[r], cnt = counts[r];
    for (int i = 0; i < cnt; i++) {
        int s = __ldg(&eidx[start + i]);
        float coef = __ldg(&dinv[s]) * dr;
        const float* hs = h + (size_t)s*stride;
        acc0 = fmaf(coef, __ldg(&hs[j0]), acc0);
        if (has1) acc1 = fmaf(coef, __ldg(&hs[j1]), acc1);
    }
    acc0 += bias[j0];
    if (doRelu) acc0 = fmaxf(acc0, 0.f);
    float* orow = out + (size_t)r*outStride;
    orow[j0] = acc0;
    if (has1) {
        acc1 += bias[j1];
        if (doRelu) acc1 = fmaxf(acc1, 0.f);
        orow[j1] = acc1;
    }
}

// dout == 1: thread per node
__global__ void gather1_kernel(const float* __restrict__ h,
                               const int* __restrict__ rowptr, const int* __restrict__ counts,
                               const int* __restrict__ eidx, const float* __restrict__ dinv,
                               const float* __restrict__ bias, float* __restrict__ out, int n)
{
    int r = blockIdx.x*blockDim.x + threadIdx.x;
    if (r >= n) return;
    float dr = dinv[r];
    float acc = h[r]*dr*dr;
    int start = rowptr[r], cnt = counts[r];
    for (int i = 0; i < cnt; i++) {
        int s = __ldg(&eidx[start + i]);
        acc = fmaf(__ldg(&dinv[s])*dr, __ldg(&h[s]), acc);
    }
    out[r] = acc + bias[0];
}

// ---------------- alpha / softmax / yh / build x2new ---------------------------
__global__ void alpha_kernel(const float* __restrict__ x1g /*stride 36*/,
                             const float* __restrict__ x2p /*stride 35*/,
                             const float* __restrict__ xfull /*stride 35*/,
                             const float* __restrict__ theta,
                             const float* __restrict__ A,
                             const float* __restrict__ smoothing,
                             float* __restrict__ x2n)
{
    __shared__ float sxk[80*35];
    __shared__ float sth[34*34];
    __shared__ float sG[16*34];
    __shared__ float ss[80];
    __shared__ float syk[64];
    __shared__ float sal[16*64];
    __shared__ float syh[16];
    const int b = blockIdx.x, tid = threadIdx.x;
    for (int i = tid; i < 34*34; i += blockDim.x) sth[i] = theta[i];
    for (int i = tid; i < 80*34; i += blockDim.x) {
        int n = i / 34, o = i - n*34;
        float v = (n < 64) ? x1g[(size_t)(b*64 + n)*36 + o]
                           : x2p[(size_t)(b*16 + (n - 64))*35 + o];
        sxk[n*35 + o] = v;
    }
    if (tid < 64) syk[tid] = xfull[(size_t)(b*64 + tid)*35 + 34];
    __syncthreads();
    if (tid < 80) {
        float s = 0.f;
        for (int o = 0; o < 34; o++) {
            float g = 0.f;
            #pragma unroll 2
            for (int O = 0; O < 34; O++) g = fmaf(sth[o*34 + O], sxk[tid*35 + O], g);
            s = fmaf(g, sxk[tid*35 + o], s);
            if (tid >= 64) sG[(tid - 64)*34 + o] = g;
        }
        ss[tid] = s;
    }
    __syncthreads();
    float sm0 = smoothing[0];
    float sig = 1.f / (1.f + expf(-sm0));
    float scale = -0.5f / (sig * 0.01f);
    for (int i = tid; i < 16*64; i += blockDim.x) {
        int q = i >> 6, p = i & 63;
        float c = 0.f;
        #pragma unroll 2
        for (int o = 0; o < 34; o++) c = fmaf(sG[q*34 + o], sxk[p*35 + o], c);
        float av = scale * (ss[p] + ss[64 + q] - 2.f*c);
        if (A[(64 + q)*80 + p] == 0.f) av = -INFINITY;
        sal[i] = av;
    }
    __syncthreads();
    const int lane = tid & 31, w = tid >> 5;
    for (int q = w; q < 16; q += 4) {
        float a0 = sal[q*64 + lane], a1 = sal[q*64 + 32 + lane];
        float mx = fmaxf(a0, a1);
        #pragma unroll
        for (int off = 16; off; off >>= 1) mx = fmaxf(mx, __shfl_xor_sync(0xffffffffu, mx, off));
        float e0 = expf(a0 - mx), e1 = expf(a1 - mx);
        float se = e0 + e1;
        float sy = e0*syk[lane] + e1*syk[32 + lane];
        #pragma unroll
        for (int off = 16; off; off >>= 1) {
            se += __shfl_xor_sync(0xffffffffu, se, off);
            sy += __shfl_xor_sync(0xffffffffu, sy, off);
        }
        if (lane == 0) syh[q] = sy / se;
    }
    __syncthreads();
    for (int i = tid; i < 16*35; i += blockDim.x) {
        int q = i / 35, c = i - q*35;
        float v = (c < 34) ? sxk[(64 + q)*35 + c] : syh[q];
        x2n[(size_t)(b*16 + q)*35 + c] = v;
    }
}

// ---------------- cd: pairwise distances, 5x5 register tile per thread ----------
__global__ void cd_kernel(const float* __restrict__ x /*stride 35*/,
                          const float* __restrict__ x2n /*stride 35*/,
                          float* __restrict__ cd)
{
    __shared__ float sxa[80*35];
    __shared__ float ssq[80];
    const int b = blockIdx.x, tid = threadIdx.x;
    for (int i = tid; i < 80*35; i += blockDim.x) {
        int n = i / 35, c = i - n*35;
        sxa[i] = (n < 64) ? x[(size_t)(b*64 + n)*35 + c]
                          : x2n[(size_t)(b*16 + (n - 64))*35 + c];
    }
    __syncthreads();
    if (tid < 80) {
        float s = 0.f;
        #pragma unroll 5
        for (int c = 0; c < 35; c++) { float v = sxa[tid*35 + c]; s = fmaf(v, v, s); }
        ssq[tid] = s;
    }
    __syncthreads();
    const int tr = tid >> 4, tc = tid & 15;
    float acc[5][5];
    #pragma unroll
    for (int i = 0; i < 5; i++)
        #pragma unroll
        for (int j = 0; j < 5; j++) acc[i][j] = 0.f;
    for (int k = 0; k < 35; k++) {
        float rv[5], cv[5];
        #pragma unroll
        for (int i = 0; i < 5; i++) rv[i] = sxa[(tr + 16*i)*35 + k];
        #pragma unroll
        for (int j = 0; j < 5; j++) cv[j] = sxa[(tc + 16*j)*35 + k];
        #pragma unroll
        for (int i = 0; i < 5; i++)
            #pragma unroll
            for (int j = 0; j < 5; j++) acc[i][j] = fmaf(rv[i], cv[j], acc[i][j]);
    }
    float* out = cd + (size_t)b*6400;
    #pragma unroll
    for (int i = 0; i < 5; i++) {
        int r = tr + 16*i;
        float sr = ssq[r];
        #pragma unroll
        for (int j = 0; j < 5; j++) {
            int c = tc + 16*j;
            float d2 = sr + ssq[c] - 2.f*acc[i][j];
            out[r*80 + c] = sqrtf(fmaxf(d2, 0.f));
        }
    }
}

// ================================================================================
extern "C" void kernel_launch(void* const* d_in, const int* in_sizes, int n_in,
                              void* d_out, int out_size)
{
    const int*   x1_cat   = (const int*)  d_in[0];
    const float* x1_num   = (const float*)d_in[1];
    const int*   x2_cat   = (const int*)  d_in[2];
    const float* x2_num   = (const float*)d_in[3];
    const int*   e1       = (const int*)  d_in[4];
    const int*   e2       = (const int*)  d_in[5];
    const float* emb0     = (const float*)d_in[6];
    const float* emb1     = (const float*)d_in[7];
    const float* emb2     = (const float*)d_in[8];
    const float* pre_W1   = (const float*)d_in[9];
    const float* pre_b1   = (const float*)d_in[10];
    const float* pre_W2   = (const float*)d_in[11];
    const float* pre_b2   = (const float*)d_in[12];
    const float* pre_W3   = (const float*)d_in[13];
    const float* pre_b3   = (const float*)d_in[14];
    const float* g1_W1    = (const float*)d_in[15];
    const float* g1_b1    = (const float*)d_in[16];
    const float* g1_W2    = (const float*)d_in[17];
    const float* g1_b2    = (const float*)d_in[18];
    const float* g2_W1    = (const float*)d_in[19];
    const float* g2_b1    = (const float*)d_in[20];
    const float* g2_W2    = (const float*)d_in[21];
    const float* g2_b2    = (const float*)d_in[22];
    const float* ker_W    = (const float*)d_in[23];
    const float* smoothing= (const float*)d_in[24];
    const float* Mmat     = (const float*)d_in[25];

    const int n1 = in_sizes[0] / 3;     // 131072
    const int n2 = in_sizes[2] / 3;     // 32768
    const int E1 = in_sizes[4] / 2;     // 1048576
    const int E2 = in_sizes[5] / 2;     // 262144
    const int* e1src = e1, *e1dst = e1 + E1;
    const int* e2src = e2, *e2dst = e2 + E2;

    float* out   = (float*)d_out;
    float* outO  = out;
    float* outCD = out + 32768;
    float* outA  = out + 32768 + 13107200;

    float *px, *px2p, *pA, *pB, *pC, *pd1, *pd2, *pth, *px2n;
    cudaGetSymbolAddress((void**)&px,   g_x);
    cudaGetSymbolAddress((void**)&px2p, g_x2p);
    cudaGetSymbolAddress((void**)&pA,   g_bufA);
    cudaGetSymbolAddress((void**)&pB,   g_bufB);
    cudaGetSymbolAddress((void**)&pC,   g_bufC);
    cudaGetSymbolAddress((void**)&pd1,  g_dinv1);
    cudaGetSymbolAddress((void**)&pd2,  g_dinv2);
    cudaGetSymbolAddress((void**)&pth,  g_theta);
    cudaGetSymbolAddress((void**)&px2n, g_x2n);
    int *pcnt1, *prp1, *pcur1, *pei1, *pcnt2, *prp2, *pcur2, *pei2, *ppart;
    cudaGetSymbolAddress((void**)&pcnt1, g_counts1);
    cudaGetSymbolAddress((void**)&prp1,  g_rowptr1);
    cudaGetSymbolAddress((void**)&pcur1, g_cursor1);
    cudaGetSymbolAddress((void**)&pei1,  g_eidx1);
    cudaGetSymbolAddress((void**)&pcnt2, g_counts2);
    cudaGetSymbolAddress((void**)&prp2,  g_rowptr2);
    cudaGetSymbolAddress((void**)&pcur2, g_cursor2);
    cudaGetSymbolAddress((void**)&pei2,  g_eidx2);
    cudaGetSymbolAddress((void**)&ppart, g_partials);

    // tiny kernels
    a_kernel<<<1, 128>>>(Mmat, outA);
    theta_kernel<<<5, 256>>>(ker_W, pth);

    // CSR build graph1
    zero_int_kernel<<<256, 256>>>(pcnt1, n1);
    count_kernel<<<(E1 + 255)/256, 256>>>(e1dst, E1, pcnt1);
    {
        int B = (n1 + 4095)/4096;
        scan1_kernel<<<B, 1024>>>(pcnt1, prp1, ppart, n1);
        scan2_kernel<<<1, 1024>>>(ppart, B);
        scan3_kernel<<<(n1 + 255)/256, 256>>>(prp1, ppart, pcnt1, pcur1, pd1, n1);
    }
    scatter_kernel<<<(E1 + 255)/256, 256>>>(e1src, e1dst, E1, pcur1, pei1);

    // CSR build graph2
    zero_int_kernel<<<64, 256>>>(pcnt2, n2);
    count_kernel<<<(E2 + 255)/256, 256>>>(e2dst, E2, pcnt2);
    {
        int B = (n2 + 4095)/4096;
        scan1_kernel<<<B, 1024>>>(pcnt2, prp2, ppart, n2);
        scan2_kernel<<<1, 1024>>>(ppart, B);
        scan3_kernel<<<(n2 + 255)/256, 256>>>(prp2, ppart, pcnt2, pcur2, pd2, n2);
    }
    scatter_kernel<<<(E2 + 255)/256, 256>>>(e2src, e2dst, E2, pcur2, pei2);

    // pre MLP for x1 and x2
    const int smemPre = (35*128 + 128*128 + 128*34 + 128 + 128 + 48) * 4;
    cudaFuncSetAttribute(pre_kernel, cudaFuncAttributeMaxDynamicSharedMemorySize, smemPre);
    pre_kernel<<<296, 256, smemPre>>>(x1_cat, x1_num, n1,
        pre_W1, pre_b1, pre_W2, pre_b2, pre_W3, pre_b3, emb0, emb1, emb2, px);
    pre_kernel<<<296, 256, smemPre>>>(x2_cat, x2_num, n2,
        pre_W1, pre_b1, pre_W2, pre_b2, pre_W3, pre_b3, emb0, emb1, emb2, px2p);

    // GCN1 layer 1: (n1,35)@(35,64), relu
    gcn_mm_kernel<<<2048, 256>>>(px, 35, 35, g1_W1, 64, n1, pA, 64);
    gather_kernel<<<(n1 + 7)/8, 256>>>(pA, 64, 64, prp1, pcnt1, pei1, pd1, g1_b1, pC, 64, n1, 1);
    // GCN1 layer 2: (n1,64)@(64,34) -> stride 36
    gcn_mm_kernel<<<2048, 256>>>(pC, 64, 64, g1_W2, 34, n1, pB, 36);
    gather_kernel<<<(n1 + 7)/8, 256>>>(pB, 36, 34, prp1, pcnt1, pei1, pd1, g1_b2, pC, 36, n1, 0);

    // alpha / softmax / yh -> x2new
    alpha_kernel<<<SBK, 128>>>(pC, px2p, px, pth, outA, smoothing, px2n);

    // GCN2 layer 1: (n2,35)@(35,64), relu
    gcn_mm_kernel<<<512, 256>>>(px2n, 35, 35, g2_W1, 64, n2, pA, 64);
    gather_kernel<<<(n2 + 7)/8, 256>>>(pA, 64, 64, prp2, pcnt2, pei2, pd2, g2_b1, pC, 64, n2, 1);
    // GCN2 layer 2: (n2,64)@(64,1) -> out
    gcn_mm_kernel<<<512, 256>>>(pC, 64, 64, g2_W2, 1, n2, pA, 1);
    gather1_kernel<<<(n2 + 255)/256, 256>>>(pA, prp2, pcnt2, pei2, pd2, g2_b2, outO, n2);

    // pairwise distances
    cd_kernel<<<SBK, 256>>>(px, px2n, outCD);
}